// round 10
// baseline (speedup 1.0000x reference)
#include <cuda_runtime.h>
#include <cuda_bf16.h>

// QuantumLinear: B=4096, IN_F=1024, NQ=4, L=2, C=256 circuits.
// Closed-form <Z_q> via Heisenberg propagation (exact).
// R7: split trig across pipes — qubits 0,2 use MUFU (__sincosf), qubits 1,3
// use an FMA-pipe polynomial sincos (Cody-Waite + deg-7/8 minimax, branchless
// magic-number quadrant extraction, no F2I/XU ops). Halves XU demand to test
// (and beat) the hidden-MUFU-pipe plateau at ~8us.

static constexpr int NCIRC = 256;
static constexpr int ROWS  = 8;     // batch rows per thread

// FMA-pipe sincos: valid for |a| < ~1e5, err ~3e-7 (tol is 1e-3).
__device__ __forceinline__ void poly_sincos(float a, float* s, float* c) {
    const float INV_PIO2 = 0.6366197723675814f;
    const float MAGIC    = 12582912.0f;              // 2^23 * 1.5
    const float PIO2_F   = 1.57079637050628662109375f; // float(pi/2), slightly > pi/2
    const float PIO2_C   = 4.37113900018624283e-8f;  // PIO2_F - pi/2

    float kf = fmaf(a, INV_PIO2, MAGIC);             // round(a*2/pi) in low mantissa
    int   q  = __float_as_int(kf);                   // low 2 bits = k mod 4
    float k  = kf - MAGIC;                           // exact float k
    float r  = fmaf(-k, PIO2_F, a);
    r = fmaf(k, PIO2_C, r);                          // r = a - k*pi/2, |r| <= pi/4

    float r2 = r * r;
    // sin(r): deg-7
    float sp = fmaf(-1.9841270114e-4f, r2, 8.3333337680e-3f);
    sp = fmaf(sp, r2, -1.6666667163e-1f);
    float s_r = fmaf(sp * r2, r, r);
    // cos(r): deg-8
    float cp = fmaf(2.4801587642e-5f, r2, -1.3888889225e-3f);
    cp = fmaf(cp, r2, 4.1666667908e-2f);
    cp = fmaf(cp, r2, -5.0e-1f);
    float c_r = fmaf(cp, r2, 1.0f);

    // quadrant: q&1 swaps, bit1 of q / q+1 gives signs
    bool sw = (q & 1);
    float ss = sw ? c_r : s_r;
    float cc = sw ? s_r : c_r;
    ss = __int_as_float(__float_as_int(ss) ^ ((unsigned)(q << 30) & 0x80000000u));
    cc = __int_as_float(__float_as_int(cc) ^ ((unsigned)((q + 1) << 30) & 0x80000000u));
    *s = ss; *c = cc;
}

__global__ void __launch_bounds__(NCIRC) qfused_kernel(
    const float4* __restrict__ x,     // (B*256) float4
    const float4* __restrict__ w4,    // (256*2) float4
    float4* __restrict__ out)         // (B*256) float4
{
    const int c = threadIdx.x;                 // circuit 0..255
    const int base = (blockIdx.x * ROWS) * NCIRC + c;

    const float4 w0 = w4[c * 2 + 0];           // alpha offsets
    const float4 w1 = w4[c * 2 + 1];           // beta angles

    // ---- per-circuit coefficients (MUFU; amortized over 8 rows) ----
    float cb0, sb0, cb1, sb1, cb2, sb2, cb3, sb3;
    __sincosf(w1.x, &sb0, &cb0);
    __sincosf(w1.y, &sb1, &cb1);
    __sincosf(w1.z, &sb2, &cb2);
    __sincosf(w1.w, &sb3, &cb3);

    const float c1c2 = cb1 * cb2;
    const float s1s2 = sb1 * sb2;
    const float a0 = c1c2 * cb3, a1 = c1c2 * sb3;
    const float a2 = s1s2 * cb3, a3 = s1s2 * sb3;
    const float p0 = cb0 * cb1,  p1 = sb0 * sb1;
    const float d0 = cb0 * c1c2, d1 = cb0 * s1s2;
    const float e0 = cb0 * c1c2 * cb3;
    const float e1 = cb0 * s1s2 * sb3;
    const float e2 = sb0 * cb1 * sb2 * sb3;
    const float e3 = sb0 * sb1 * cb2 * cb3;

#pragma unroll
    for (int r = 0; r < ROWS; r++) {
        const float4 xv = x[base + r * NCIRC];

        float S0, C0, S1, C1, S2, C2, S3, C3;
        __sincosf(xv.x + w0.x, &S0, &C0);        // XU pipe
        poly_sincos(xv.y + w0.y, &S1, &C1);      // FMA pipe
        __sincosf(xv.z + w0.z, &S2, &C2);        // XU pipe
        poly_sincos(xv.w + w0.w, &S3, &C3);      // FMA pipe

        const float C1C3 = C1 * C3;
        const float S1S3 = S1 * S3;
        const float C0C2 = C0 * C2;
        const float S0S2 = S0 * S2;

        float4 z;
        z.x = fmaf(C1C3, fmaf(a0, C0, a3 * S0), S1S3 * fmaf(a1, S0, a2 * C0));
        z.y = C3 * fmaf(p0, C0C2, p1 * S0S2);
        z.z = fmaf(d0, C1C3, d1 * S1S3);
        z.w = fmaf(C2, fmaf(e0, C0, e1 * S0), S2 * fmaf(e2, C0, e3 * S0));

        out[base + r * NCIRC] = z;
    }
}

extern "C" void kernel_launch(void* const* d_in, const int* in_sizes, int n_in,
                              void* d_out, int out_size) {
    const float* x = (const float*)d_in[0];       // (4096, 1024) f32
    const float* w = (const float*)d_in[1];       // (256, 2, 4)  f32
    float* out = (float*)d_out;                   // (4096, 1024) f32

    const int B = 4096;
    qfused_kernel<<<B / ROWS, NCIRC>>>(
        (const float4*)x, (const float4*)w, (float4*)out);
}